// round 1
// baseline (speedup 1.0000x reference)
#include <cuda_runtime.h>
#include <cstdint>

// Problem constants (fixed by the dataset)
#define K1      100     // first-layer K (k-NN fan-in)
#define H       256     // hidden width
#define ROWS    64      // rows (nodes) per block
#define RPAD    68      // smem row stride in floats (multiple of 4 for LDS.128)
#define KBS     32      // K-slab size staged per chunk
#define THREADS 512

// Smem layout (floats):
//   hA  : H*RPAD            (activation buffer A, [k][r] transposed)
//   hB  : H*RPAD            (activation buffer B; also aliases the e-tile)
//   Ws2 : KBS*2048 bytes    (weight slab, duplicated f32x2 pairs, ull2-element layout)
#define SMEM_FLOATS (2 * H * RPAD)
#define SMEM_BYTES  (SMEM_FLOATS * 4 + KBS * 2048)

__device__ __forceinline__ unsigned long long pack2(float lo, float hi) {
    unsigned long long r;
    asm("mov.b64 %0, {%1,%2};" : "=l"(r) : "f"(lo), "f"(hi));
    return r;
}
__device__ __forceinline__ void unpack2(unsigned long long v, float& lo, float& hi) {
    asm("mov.b64 {%0,%1}, %2;" : "=f"(lo), "=f"(hi) : "l"(v));
}
// d += a * b elementwise on packed f32x2 (Blackwell FFMA2; ptxas never auto-fuses this)
__device__ __forceinline__ void fma2(unsigned long long& d, unsigned long long a,
                                     unsigned long long b) {
    asm("fma.rn.f32x2 %0, %1, %2, %0;" : "+l"(d) : "l"(a), "l"(b));
}

// One MLP layer: h_out[j][r] = tanh( sum_k h_in[k][r] * W[k][j] + b[j] )
// h_in/h_out are smem, [k][r]-major with stride RPAD. W,b in global (L2-resident).
// Thread (cg = tid&63, rg = tid>>6) owns cols j = cg*4..cg*4+3, rows r = rg*8..rg*8+7.
__device__ __forceinline__ void mlp_layer(
    const float* __restrict__ Wg, const float* __restrict__ bg,
    const float* h_in, float* h_out, unsigned long long* Ws2, int Kdim,
    int cg, int rg)
{
    unsigned long long acc[4][4];
#pragma unroll
    for (int jj = 0; jj < 4; jj++) {
        float bj = bg[cg * 4 + jj];
        unsigned long long bp = pack2(bj, bj);
#pragma unroll
        for (int rp = 0; rp < 4; rp++) acc[jj][rp] = bp;
    }

    const ulonglong2* Ws2v = (const ulonglong2*)Ws2;
    float* Wsf = (float*)Ws2;

    for (int kb = 0; kb < Kdim; kb += KBS) {
        int kc = min(KBS, Kdim - kb);
        __syncthreads();   // previous chunk's readers done before restaging Ws2
        // Stage W slab [kb..kb+kc) x H, duplicated into f32x2 pairs.
        // ull2 element (k, ph, cg16) holds floats {W[k][j],W[k][j],W[k][j+1],W[k][j+1]}
        // at element index (k*2+ph)*64 + j/4, with ph=(j&3)>>1.
        for (int idx = threadIdx.x; idx < kc * H; idx += THREADS) {
            int k = idx >> 8;
            int j = idx & (H - 1);
            float w = Wg[(kb + k) * H + j];
            int ebase = (((k * 2 + ((j & 3) >> 1)) * 64 + (j >> 2)) << 2) + ((j & 1) * 2);
            Wsf[ebase] = w;
            Wsf[ebase + 1] = w;
        }
        __syncthreads();

        const char* hbase = (const char*)(h_in + (size_t)kb * RPAD + rg * 8);
        if (kc == KBS) {
#pragma unroll
            for (int k = 0; k < KBS; k++) {
                ulonglong2 ha = *(const ulonglong2*)(hbase + (size_t)k * (RPAD * 4));      // {h(r0,r0+1), h(r0+2,r0+3)}
                ulonglong2 hb = *(const ulonglong2*)(hbase + (size_t)k * (RPAD * 4) + 16); // {h(r0+4,..), h(r0+6,..)}
                ulonglong2 wa = Ws2v[(k * 2) * 64 + cg];     // {dup(w_j0), dup(w_j1)}
                ulonglong2 wb = Ws2v[(k * 2 + 1) * 64 + cg]; // {dup(w_j2), dup(w_j3)}
                fma2(acc[0][0], ha.x, wa.x); fma2(acc[0][1], ha.y, wa.x);
                fma2(acc[0][2], hb.x, wa.x); fma2(acc[0][3], hb.y, wa.x);
                fma2(acc[1][0], ha.x, wa.y); fma2(acc[1][1], ha.y, wa.y);
                fma2(acc[1][2], hb.x, wa.y); fma2(acc[1][3], hb.y, wa.y);
                fma2(acc[2][0], ha.x, wb.x); fma2(acc[2][1], ha.y, wb.x);
                fma2(acc[2][2], hb.x, wb.x); fma2(acc[2][3], hb.y, wb.x);
                fma2(acc[3][0], ha.x, wb.y); fma2(acc[3][1], ha.y, wb.y);
                fma2(acc[3][2], hb.x, wb.y); fma2(acc[3][3], hb.y, wb.y);
            }
        } else {
            for (int k = 0; k < kc; k++) {
                ulonglong2 ha = *(const ulonglong2*)(hbase + (size_t)k * (RPAD * 4));
                ulonglong2 hb = *(const ulonglong2*)(hbase + (size_t)k * (RPAD * 4) + 16);
                ulonglong2 wa = Ws2v[(k * 2) * 64 + cg];
                ulonglong2 wb = Ws2v[(k * 2 + 1) * 64 + cg];
                fma2(acc[0][0], ha.x, wa.x); fma2(acc[0][1], ha.y, wa.x);
                fma2(acc[0][2], hb.x, wa.x); fma2(acc[0][3], hb.y, wa.x);
                fma2(acc[1][0], ha.x, wa.y); fma2(acc[1][1], ha.y, wa.y);
                fma2(acc[1][2], hb.x, wa.y); fma2(acc[1][3], hb.y, wa.y);
                fma2(acc[2][0], ha.x, wb.x); fma2(acc[2][1], ha.y, wb.x);
                fma2(acc[2][2], hb.x, wb.x); fma2(acc[2][3], hb.y, wb.x);
                fma2(acc[3][0], ha.x, wb.y); fma2(acc[3][1], ha.y, wb.y);
                fma2(acc[3][2], hb.x, wb.y); fma2(acc[3][3], hb.y, wb.y);
            }
        }
    }

    // Epilogue: tanh + store transposed [j][r]
#pragma unroll
    for (int jj = 0; jj < 4; jj++) {
        float v0, v1, v2, v3, v4, v5, v6, v7;
        unpack2(acc[jj][0], v0, v1);
        unpack2(acc[jj][1], v2, v3);
        unpack2(acc[jj][2], v4, v5);
        unpack2(acc[jj][3], v6, v7);
        v0 = tanhf(v0); v1 = tanhf(v1); v2 = tanhf(v2); v3 = tanhf(v3);
        v4 = tanhf(v4); v5 = tanhf(v5); v6 = tanhf(v6); v7 = tanhf(v7);
        float* dst = h_out + (size_t)(cg * 4 + jj) * RPAD + rg * 8;
        ((float4*)dst)[0] = make_float4(v0, v1, v2, v3);
        ((float4*)dst)[1] = make_float4(v4, v5, v6, v7);
    }
}

__global__ void __launch_bounds__(THREADS, 1)
gnn_mlp_kernel(const float* __restrict__ ea,
               const float* __restrict__ W1, const float* __restrict__ b1,
               const float* __restrict__ W2, const float* __restrict__ b2,
               const float* __restrict__ W3, const float* __restrict__ b3,
               const float* __restrict__ W4, const float* __restrict__ b4,
               float* __restrict__ out, int ntot)
{
    extern __shared__ float smem[];
    float* hA = smem;                 // H*RPAD
    float* hB = smem + H * RPAD;      // H*RPAD, also holds the e-tile for layer 1
    unsigned long long* Ws2 = (unsigned long long*)(smem + 2 * H * RPAD);

    int row0 = blockIdx.x * ROWS;
    int cg = threadIdx.x & 63;
    int rg = threadIdx.x >> 6;

    // Load e-tile (ROWS x K1) from edge_attr, stored transposed [k][r] in hB.
    for (int idx = threadIdx.x; idx < ROWS * K1; idx += THREADS) {
        int r = idx / K1;
        int k = idx - r * K1;
        int row = row0 + r;
        float v = (row < ntot) ? ea[(size_t)row * K1 + k] : 0.0f;
        hB[k * RPAD + r] = v;
    }
    // (mlp_layer's leading __syncthreads() makes these writes visible)

    mlp_layer(W1, b1, hB, hA, Ws2, K1, cg, rg);   // layer 1: e -> hA
    mlp_layer(W2, b2, hA, hB, Ws2, H, cg, rg);    // layer 2: hA -> hB
    mlp_layer(W3, b3, hB, hA, Ws2, H, cg, rg);    // layer 3: hB -> hA

    // Layer 4: out[r] = sigmoid( sum_k hA[k][r]*W4[k] + b4 )
    __syncthreads();  // layer-3 readers done before reusing Ws2 for W4
    float* w4s = (float*)Ws2;
    for (int idx = threadIdx.x; idx < H; idx += THREADS) w4s[idx] = W4[idx];
    __syncthreads();

    if (threadIdx.x < ROWS) {
        int r = threadIdx.x;
        float a0 = 0.f, a1 = 0.f, a2 = 0.f, a3 = 0.f;
#pragma unroll 8
        for (int k = 0; k < H; k += 4) {
            a0 += hA[(k + 0) * RPAD + r] * w4s[k + 0];
            a1 += hA[(k + 1) * RPAD + r] * w4s[k + 1];
            a2 += hA[(k + 2) * RPAD + r] * w4s[k + 2];
            a3 += hA[(k + 3) * RPAD + r] * w4s[k + 3];
        }
        float z = (a0 + a1) + (a2 + a3) + b4[0];
        int row = row0 + r;
        if (row < ntot) out[row] = 1.0f / (1.0f + expf(-z));
    }
}

extern "C" void kernel_launch(void* const* d_in, const int* in_sizes, int n_in,
                              void* d_out, int out_size)
{
    // Input order per metadata: x, edge_index, edge_attr, W1, b1, W2, b2, W3, b3, W4, b4
    // x and edge_index never enter the math (see reference) — skipped entirely.
    const float* ea = (const float*)d_in[2];
    const float* W1 = (const float*)d_in[3];
    const float* b1 = (const float*)d_in[4];
    const float* W2 = (const float*)d_in[5];
    const float* b2 = (const float*)d_in[6];
    const float* W3 = (const float*)d_in[7];
    const float* b3 = (const float*)d_in[8];
    const float* W4 = (const float*)d_in[9];
    const float* b4 = (const float*)d_in[10];
    float* out = (float*)d_out;

    int ntot = out_size;                       // N = 500000
    int grid = (ntot + ROWS - 1) / ROWS;       // 7813 blocks

    cudaFuncSetAttribute(gnn_mlp_kernel,
                         cudaFuncAttributeMaxDynamicSharedMemorySize, SMEM_BYTES);
    gnn_mlp_kernel<<<grid, THREADS, SMEM_BYTES>>>(ea, W1, b1, W2, b2, W3, b3,
                                                  W4, b4, out, ntot);
}